// round 6
// baseline (speedup 1.0000x reference)
#include <cuda_runtime.h>
#include <cuda_fp16.h>
#include <math.h>

#define R 256
#define F4 32           // 128 features = 32 float4
#define NPIX (R * R)

// Static device scratch
__device__ uint2 g_tmph[5 * (size_t)NPIX * F4];  // row-blurred levels, fp16x4 (84 MB)
__device__ uint4 g_Hh[(size_t)NPIX * 16];        // H = G@W1+b1, fp16 (16.8 MB)
__device__ uint2 g_W1p[64 * 128];                // W1 tf32 B-fragments (64 KB)

// ---------------------------------------------------------------------------
// Compile-time gaussian weights -> FFMA-immediate taps
// ---------------------------------------------------------------------------
constexpr double cexp_d(double x) {   // x <= 0
    double r = x; int k = 0;
    while (r < -0.34657359027997264) { r += 0.69314718055994530942; k++; }
    double term = 1.0, sum = 1.0;
    for (int i = 1; i < 22; i++) { term *= r / (double)i; sum += term; }
    for (int i = 0; i < k; i++) sum *= 0.5;
    return sum;
}

template <int S> struct GWt {
    float w[S];
    constexpr GWt() : w{} {
        double t[S] = {};
        double sum = 0.0;
        for (int n = 0; n < S; n++) {
            double xx = ((double)n - (double)(S - 1) * 0.5) / ((double)S * 0.5);
            t[n] = cexp_d(-0.5 * xx * xx);
            sum += t[n];
        }
        for (int n = 0; n < S; n++) w[n] = (float)(t[n] / sum);
    }
};

__device__ __forceinline__ int reflect_i(int c) {
    c = (c < 0) ? -c : c;
    return (c > R - 1) ? (2 * (R - 1) - c) : c;
}

__device__ __forceinline__ uint2 pack4(float4 v) {
    __half2 a = __floats2half2_rn(v.x, v.y);
    __half2 b = __floats2half2_rn(v.z, v.w);
    uint2 r;
    r.x = *reinterpret_cast<unsigned*>(&a);
    r.y = *reinterpret_cast<unsigned*>(&b);
    return r;
}

__device__ __forceinline__ float4 unpack4(uint2 u) {
    __half2 a = *reinterpret_cast<__half2*>(&u.x);
    __half2 b = *reinterpret_cast<__half2*>(&u.y);
    float2 fa = __half22float2(a);
    float2 fb = __half22float2(b);
    return make_float4(fa.x, fa.y, fb.x, fb.y);
}

__device__ __forceinline__ unsigned f2tf32(float f) {
    unsigned u;
    asm("cvt.rna.tf32.f32 %0, %1;" : "=r"(u) : "f"(f));
    return u;
}

__device__ __forceinline__ void mma_tf32(float* d, unsigned a0, unsigned a1,
                                         unsigned a2, unsigned a3,
                                         unsigned b0, unsigned b1) {
    asm("mma.sync.aligned.m16n8k8.row.col.f32.tf32.tf32.f32 "
        "{%0,%1,%2,%3},{%4,%5,%6,%7},{%8,%9},{%0,%1,%2,%3};"
        : "+f"(d[0]), "+f"(d[1]), "+f"(d[2]), "+f"(d[3])
        : "r"(a0), "r"(a1), "r"(a2), "r"(a3), "r"(b0), "r"(b1));
}

// ---------------------------------------------------------------------------
// W1 -> tf32 B-fragments in global (L1-resident during MMA)
// ---------------------------------------------------------------------------
__global__ void k_w1prep(const float* __restrict__ W1) {
    int t = blockIdx.x * 256 + threadIdx.x;   // 8192
    int rr = t >> 7;
    int n  = t & 127;
    int kk = rr >> 2, tig = rr & 3;
    uint2 v;
    v.x = f2tf32(W1[(kk * 8 + tig) * 128 + n]);
    v.y = f2tf32(W1[(kk * 8 + tig + 4) * 128 + n]);
    g_W1p[rr * 128 + n] = v;
}

// ---------------------------------------------------------------------------
// Row pass (R4 structure + immediate weights): block = (col j, 64-row tile).
// 512 threads, 4 rows/thread, fp32 smem staging.
// ---------------------------------------------------------------------------
template <int S>
__device__ __forceinline__ void row_level(const float4 (*sh)[F4],
                                          int base, int f4, int lvl, int i0, int j)
{
    constexpr GWt<S> gw{};
    float4 acc[4];
#pragma unroll
    for (int q = 0; q < 4; q++) acc[q] = make_float4(0.f, 0.f, 0.f, 0.f);
#pragma unroll
    for (int r = 0; r < 4 + S - 1; r++) {
        float4 v = sh[base + 16 - S / 2 + r][f4];
#pragma unroll
        for (int q = 0; q < 4; q++) {
            int jj = r - q;
            if (jj >= 0 && jj < S) {
                float k = gw.w[jj];              // immediate operand
                acc[q].x += k * v.x; acc[q].y += k * v.y;
                acc[q].z += k * v.z; acc[q].w += k * v.w;
            }
        }
    }
    size_t lb = (size_t)lvl * NPIX * F4;
#pragma unroll
    for (int q = 0; q < 4; q++)
        g_tmph[lb + ((size_t)(i0 + base + q) * R + j) * F4 + f4] = pack4(acc[q]);
}

__global__ void __launch_bounds__(512, 2) k_rows(const float4* __restrict__ in)
{
    __shared__ float4 sh[96][F4];
    int j  = blockIdx.x;
    int i0 = blockIdx.y * 64;
    int t  = threadIdx.x;
    int f4 = t & 31, tg = t >> 5;           // tg 0..15

    for (int rr = tg; rr < 96; rr += 16) {
        int c = reflect_i(i0 - 16 + rr);
        sh[rr][f4] = in[((size_t)c * R + j) * F4 + f4];
    }
    __syncthreads();

    int base = tg * 4;
    row_level<2 >(sh, base, f4, 0, i0, j);
    row_level<4 >(sh, base, f4, 1, i0, j);
    row_level<8 >(sh, base, f4, 2, i0, j);
    row_level<16>(sh, base, f4, 3, i0, j);
    row_level<32>(sh, base, f4, 4, i0, j);
}

// ---------------------------------------------------------------------------
// Col pass + H GEMM fused. Block = (row i, 128-col half), 512 threads/16 warps.
// smem: sh float4[160][32] = 81920 @ 0   (stage, b_l prescaled; reused as Hs)
//       Gs  uint[128*132]  = 67584 @ 81920
//       b1s float[128]     =   512 @ 149504
// total 150016
// ---------------------------------------------------------------------------
#define SMEM_CH 150016

template <int S>
__device__ __forceinline__ void col_acc(const float4 (*sh)[F4],
                                        int base, int f4, float4* acc)
{
    constexpr GWt<S> gw{};
#pragma unroll
    for (int r = 0; r < 8 + S - 1; r++) {
        float4 v = sh[base + 16 - S / 2 + r][f4];
#pragma unroll
        for (int q = 0; q < 8; q++) {
            int jj = r - q;
            if (jj >= 0 && jj < S) {
                float k = gw.w[jj];              // immediate operand
                acc[q].x += k * v.x; acc[q].y += k * v.y;
                acc[q].z += k * v.z; acc[q].w += k * v.w;
            }
        }
    }
}

__global__ void __launch_bounds__(512, 1) k_colsH(const float4* __restrict__ base4,
                                                  const float* __restrict__ b_levels,
                                                  const float* __restrict__ b1)
{
    extern __shared__ unsigned char smem_raw[];
    float4 (*sh)[F4] = (float4 (*)[F4])smem_raw;     // [160][32]
    unsigned* Gs     = (unsigned*)(smem_raw + 81920);
    float*    b1s    = (float*)(smem_raw + 149504);

    int i  = blockIdx.y;
    int j0 = blockIdx.x * 128;
    int t  = threadIdx.x;
    int f4 = t & 31, tg = t >> 5;    // tg 0..15
    int base = tg * 8;               // local col 0..120

    if (t < 128) b1s[t] = b1[t];

    float b0 = b_levels[0];
    float4 acc[8];
#pragma unroll
    for (int q = 0; q < 8; q++) {
        float4 v = base4[((size_t)i * R + j0 + base + q) * F4 + f4];
        acc[q] = make_float4(b0 * v.x, b0 * v.y, b0 * v.z, b0 * v.w);
    }

    // levels 1..5: stage = bl * tmph_row (fp32 smem), immediate-weight col blur
#pragma unroll
    for (int lvl = 1; lvl <= 5; lvl++) {
        float bl = b_levels[lvl];
        size_t lb = (size_t)(lvl - 1) * NPIX * F4 + (size_t)i * R * F4;
        __syncthreads();
        for (int rr = tg; rr < 160; rr += 16) {
            int c = reflect_i(j0 - 16 + rr);
            float4 v = unpack4(g_tmph[lb + (size_t)c * F4 + f4]);
            sh[rr][f4] = make_float4(bl * v.x, bl * v.y, bl * v.z, bl * v.w);
        }
        __syncthreads();
        switch (lvl) {
            case 1: col_acc<2 >(sh, base, f4, acc); break;
            case 2: col_acc<4 >(sh, base, f4, acc); break;
            case 3: col_acc<8 >(sh, base, f4, acc); break;
            case 4: col_acc<16>(sh, base, f4, acc); break;
            case 5: col_acc<32>(sh, base, f4, acc); break;
        }
    }

    // Store G tile as tf32 (stride 132 words)
#pragma unroll
    for (int q = 0; q < 8; q++) {
        uint4 u;
        u.x = f2tf32(acc[q].x); u.y = f2tf32(acc[q].y);
        u.z = f2tf32(acc[q].z); u.w = f2tf32(acc[q].w);
        *reinterpret_cast<uint4*>(&Gs[(base + q) * 132 + 4 * f4]) = u;
    }
    __syncthreads();

    // MMA: 128x128 per block. 16 warps: mt = w&7 (m-tile of 16), nh = w>>3.
    int w    = t >> 5;
    int lane = t & 31;
    int mt   = w & 7;
    int nh   = w >> 3;
    int g    = lane >> 2;
    int tig  = lane & 3;

    float d[8][4];
#pragma unroll
    for (int nt = 0; nt < 8; nt++)
#pragma unroll
        for (int e = 0; e < 4; e++) d[nt][e] = 0.0f;

#pragma unroll 4
    for (int kk = 0; kk < 16; kk++) {
        int arow = (mt * 16 + g) * 132 + kk * 8 + tig;
        unsigned a0 = Gs[arow];
        unsigned a1 = Gs[arow + 8 * 132];
        unsigned a2 = Gs[arow + 4];
        unsigned a3 = Gs[arow + 8 * 132 + 4];
        int brow = (kk * 4 + tig) * 128 + nh * 64 + g;
#pragma unroll
        for (int nt = 0; nt < 8; nt++) {
            uint2 b = g_W1p[brow + nt * 8];
            mma_tf32(d[nt], a0, a1, a2, a3, b.x, b.y);
        }
    }
    __syncthreads();   // done reading sh -> reuse as Hs

    // Epilogue: +b1, fp16 pack into Hs [128][68] half2
    __half2* Hs2 = (__half2*)smem_raw;
    int m0 = mt * 16 + g;
#pragma unroll
    for (int nt = 0; nt < 8; nt++) {
        int n0 = nh * 64 + nt * 8 + 2 * tig;
        float bb0 = b1s[n0], bb1 = b1s[n0 + 1];
        Hs2[m0 * 68 + (n0 >> 1)]       = __floats2half2_rn(d[nt][0] + bb0,
                                                           d[nt][1] + bb1);
        Hs2[(m0 + 8) * 68 + (n0 >> 1)] = __floats2half2_rn(d[nt][2] + bb0,
                                                           d[nt][3] + bb1);
    }
    __syncthreads();

    // Coalesced fp16 H store: 128 pixels x 16 uint4 (row stride 17 uint4)
    const uint4* Hs4 = (const uint4*)smem_raw;
#pragma unroll
    for (int it = 0; it < 4; it++) {
        int idx = it * 512 + t;
        int p  = idx >> 4;
        int q4 = idx & 15;
        g_Hh[((size_t)i * R + j0 + p) * 16 + q4] = Hs4[p * 17 + q4];
    }
}

// ---------------------------------------------------------------------------
// Points: bilerp gather of fp16 H + relu + W2 + b2. W2 in smem (low regs).
// ---------------------------------------------------------------------------
__global__ void __launch_bounds__(256) k_pts(const float* __restrict__ pt,
                                             const float4* __restrict__ W2v,
                                             const float* __restrict__ b2,
                                             float4* __restrict__ out4)
{
    __shared__ float4 w2s[128];
    int t = threadIdx.x, lane = t & 31, w = t >> 5;
    int lh = lane >> 4;
    int lf = lane & 15;

    if (t < 128) w2s[t] = W2v[t];
    __syncthreads();

    float b20 = b2[0], b21 = b2[1], b22 = b2[2], b23 = b2[3];

    int p0 = blockIdx.x * 128 + w * 16 + lh;
#pragma unroll 2
    for (int it = 0; it < 8; it++) {
        int p = p0 + it * 2;
        float px = pt[2 * p];
        float py = pt[2 * p + 1];
        float ax = (px + 1.0f) / 2.0f * 255.0f;
        float ay = (py + 1.0f) / 2.0f * 255.0f;
        int ix = (int)ax; if (ix > 255) ix = 255;
        int iy = (int)ay; if (iy > 255) iy = 255;
        float fx = ax - (float)ix;
        float fy = ay - (float)iy;
        int ix1 = (ix + 1 > 255) ? 255 : ix + 1;
        int iy1 = (iy + 1 > 255) ? 255 : iy + 1;
        float w00 = (1.0f - fx) * (1.0f - fy);
        float w01 = (1.0f - fx) * fy;
        float w10 = fx * (1.0f - fy);
        float w11 = fx * fy;

        uint4 c00 = g_Hh[((size_t)(ix  * R + iy )) * 16 + lf];
        uint4 c01 = g_Hh[((size_t)(ix  * R + iy1)) * 16 + lf];
        uint4 c10 = g_Hh[((size_t)(ix1 * R + iy )) * 16 + lf];
        uint4 c11 = g_Hh[((size_t)(ix1 * R + iy1)) * 16 + lf];

        float v[8];
#pragma unroll
        for (int k = 0; k < 8; k++) v[k] = 0.0f;
        {
            const unsigned* cs[4] = {&c00.x, &c01.x, &c10.x, &c11.x};
            float ws[4] = {w00, w01, w10, w11};
#pragma unroll
            for (int cc = 0; cc < 4; cc++) {
                float wgt = ws[cc];
#pragma unroll
                for (int k = 0; k < 4; k++) {
                    __half2 h = *reinterpret_cast<const __half2*>(&cs[cc][k]);
                    float2 f = __half22float2(h);
                    v[2 * k]     += wgt * f.x;
                    v[2 * k + 1] += wgt * f.y;
                }
            }
        }

        float4 o = make_float4(0.f, 0.f, 0.f, 0.f);
#pragma unroll
        for (int j = 0; j < 8; j++) {
            float h = fmaxf(v[j], 0.0f);
            float4 w2r = w2s[lf * 8 + j];
            o.x += h * w2r.x; o.y += h * w2r.y;
            o.z += h * w2r.z; o.w += h * w2r.w;
        }

#pragma unroll
        for (int off = 8; off; off >>= 1) {
            o.x += __shfl_xor_sync(0xffffffffu, o.x, off);
            o.y += __shfl_xor_sync(0xffffffffu, o.y, off);
            o.z += __shfl_xor_sync(0xffffffffu, o.z, off);
            o.w += __shfl_xor_sync(0xffffffffu, o.w, off);
        }
        if (lf == 0)
            out4[p] = make_float4(o.x + b20, o.y + b21, o.z + b22, o.w + b23);
    }
}

// ---------------------------------------------------------------------------
extern "C" void kernel_launch(void* const* d_in, const int* in_sizes, int n_in,
                              void* d_out, int out_size) {
    const float*  pt       = (const float*)d_in[0];
    const float4* base4    = (const float4*)d_in[1];
    const float*  b_levels = (const float*)d_in[2];
    const float*  W1       = (const float*)d_in[3];
    const float*  b1       = (const float*)d_in[4];
    const float*  W2       = (const float*)d_in[5];
    const float*  b2       = (const float*)d_in[6];
    float* out             = (float*)d_out;

    cudaFuncSetAttribute(k_colsH, cudaFuncAttributeMaxDynamicSharedMemorySize,
                         SMEM_CH);

    k_w1prep<<<32, 256>>>(W1);

    dim3 bg(256, 4);
    k_rows<<<bg, 512>>>(base4);

    dim3 cg(2, 256);
    k_colsH<<<cg, 512, SMEM_CH>>>(base4, b_levels, b1);

    k_pts<<<2048, 256>>>(pt, (const float4*)W2, b2, (float4*)out);
}

// round 7
// speedup vs baseline: 1.1776x; 1.1776x over previous
#include <cuda_runtime.h>
#include <cuda_fp16.h>
#include <math.h>

#define R 256
#define F4 32           // 128 features = 32 float4
#define NPIX (R * R)

// Static device scratch
__device__ uint2 g_tmph[5 * (size_t)NPIX * F4];  // row-blurred levels, fp16x4 (84 MB)
__device__ uint4 g_Hh[(size_t)NPIX * 16];        // H = G@W1+b1, fp16 (16.8 MB)

struct KW { float w[62]; };   // gaussian windows, offset s-2

__device__ __forceinline__ int reflect_i(int c) {
    c = (c < 0) ? -c : c;
    return (c > R - 1) ? (2 * (R - 1) - c) : c;
}

__device__ __forceinline__ uint2 pack4(float4 v) {
    __half2 a = __floats2half2_rn(v.x, v.y);
    __half2 b = __floats2half2_rn(v.z, v.w);
    uint2 r;
    r.x = *reinterpret_cast<unsigned*>(&a);
    r.y = *reinterpret_cast<unsigned*>(&b);
    return r;
}

__device__ __forceinline__ float4 unpack4(uint2 u) {
    __half2 a = *reinterpret_cast<__half2*>(&u.x);
    __half2 b = *reinterpret_cast<__half2*>(&u.y);
    float2 fa = __half22float2(a);
    float2 fb = __half22float2(b);
    return make_float4(fa.x, fa.y, fb.x, fb.y);
}

__device__ __forceinline__ unsigned f2tf32(float f) {
    unsigned u;
    asm("cvt.rna.tf32.f32 %0, %1;" : "=r"(u) : "f"(f));
    return u;
}

__device__ __forceinline__ void mma_tf32(float* d, unsigned a0, unsigned a1,
                                         unsigned a2, unsigned a3,
                                         unsigned b0, unsigned b1) {
    asm("mma.sync.aligned.m16n8k8.row.col.f32.tf32.tf32.f32 "
        "{%0,%1,%2,%3},{%4,%5,%6,%7},{%8,%9},{%0,%1,%2,%3};"
        : "+f"(d[0]), "+f"(d[1]), "+f"(d[2]), "+f"(d[3])
        : "r"(a0), "r"(a1), "r"(a2), "r"(a3), "r"(b0), "r"(b1));
}

// ---------------------------------------------------------------------------
// Row pass, all 5 levels fused. 512 threads, 4 rows per thread.  (R4 exact)
// ---------------------------------------------------------------------------
template <int S>
__device__ __forceinline__ void row_level(const float4 (*sh)[F4], const KW& kw,
                                          int base, int f4, int lvl, int i0, int j)
{
    float4 acc[4];
#pragma unroll
    for (int q = 0; q < 4; q++) acc[q] = make_float4(0.f, 0.f, 0.f, 0.f);
#pragma unroll
    for (int r = 0; r < 4 + S - 1; r++) {
        float4 v = sh[base + 16 - S / 2 + r][f4];
#pragma unroll
        for (int q = 0; q < 4; q++) {
            int jj = r - q;
            if (jj >= 0 && jj < S) {
                float k = kw.w[S - 2 + jj];
                acc[q].x += k * v.x; acc[q].y += k * v.y;
                acc[q].z += k * v.z; acc[q].w += k * v.w;
            }
        }
    }
    size_t lb = (size_t)lvl * NPIX * F4;
#pragma unroll
    for (int q = 0; q < 4; q++)
        g_tmph[lb + ((size_t)(i0 + base + q) * R + j) * F4 + f4] = pack4(acc[q]);
}

__global__ void __launch_bounds__(512, 2) k_rows(const float4* __restrict__ in, KW kw)
{
    __shared__ float4 sh[96][F4];
    int j  = blockIdx.x;
    int i0 = blockIdx.y * 64;
    int t  = threadIdx.x;
    int f4 = t & 31, tg = t >> 5;           // tg 0..15

    for (int rr = tg; rr < 96; rr += 16) {
        int c = reflect_i(i0 - 16 + rr);
        sh[rr][f4] = in[((size_t)c * R + j) * F4 + f4];
    }
    __syncthreads();

    int base = tg * 4;
    row_level<2 >(sh, kw, base, f4, 0, i0, j);
    row_level<4 >(sh, kw, base, f4, 1, i0, j);
    row_level<8 >(sh, kw, base, f4, 2, i0, j);
    row_level<16>(sh, kw, base, f4, 3, i0, j);
    row_level<32>(sh, kw, base, f4, 4, i0, j);
}

// ---------------------------------------------------------------------------
// Col pass + H GEMM fused (R4 exact).
// ---------------------------------------------------------------------------
#define SMEM_CH 151040

template <int S>
__device__ __forceinline__ void col_load(float4 (*sh)[F4], int lvl, int i, int j0,
                                         int f4, int tg)
{
    size_t lb = (size_t)lvl * NPIX * F4;
#pragma unroll
    for (int rr = tg; rr < 96; rr += 8) {
        int c = reflect_i(j0 - 16 + rr);
        sh[rr][f4] = unpack4(g_tmph[lb + ((size_t)i * R + c) * F4 + f4]);
    }
}

template <int S>
__device__ __forceinline__ void col_acc(const float4 (*sh)[F4], const KW& kw,
                                        float bl, int base, int f4, float4* acc)
{
    float kr[S];
#pragma unroll
    for (int n = 0; n < S; n++) kr[n] = bl * kw.w[S - 2 + n];
#pragma unroll
    for (int r = 0; r < 8 + S - 1; r++) {
        float4 v = sh[base + 16 - S / 2 + r][f4];
#pragma unroll
        for (int q = 0; q < 8; q++) {
            int jj = r - q;
            if (jj >= 0 && jj < S) {
                float k = kr[jj];
                acc[q].x += k * v.x; acc[q].y += k * v.y;
                acc[q].z += k * v.z; acc[q].w += k * v.w;
            }
        }
    }
}

__global__ void __launch_bounds__(256, 1) k_colsH(const float4* __restrict__ base4,
                                                  const float* __restrict__ b_levels,
                                                  const float* __restrict__ W1,
                                                  const float* __restrict__ b1,
                                                  KW kw)
{
    extern __shared__ unsigned char smem_raw[];
    float4 (*sh)[F4]   = (float4 (*)[F4])smem_raw;
    uint2*    W1p      = (uint2*)(smem_raw + 49152);
    unsigned* Gs       = (unsigned*)(smem_raw + 116736);
    float*    b1s      = (float*)(smem_raw + 150528);

    int i  = blockIdx.x;
    int j0 = blockIdx.y * 64;
    int t  = threadIdx.x;
    int f4 = t & 31, tg = t >> 5;
    int base = tg * 8;

#pragma unroll
    for (int it = 0; it < 32; it++) {
        int task = it * 256 + t;
        int r = task >> 7;
        int n = task & 127;
        int klo = 8 * (r >> 2) + (r & 3);
        uint2 v;
        v.x = f2tf32(W1[klo * 128 + n]);
        v.y = f2tf32(W1[(klo + 4) * 128 + n]);
        W1p[r * 132 + n] = v;
    }
    if (t < 128) b1s[t] = b1[t];

    float b0 = b_levels[0];
    float4 acc[8];
#pragma unroll
    for (int q = 0; q < 8; q++) {
        float4 v = base4[((size_t)i * R + (j0 + base + q)) * F4 + f4];
        acc[q] = make_float4(b0 * v.x, b0 * v.y, b0 * v.z, b0 * v.w);
    }

    col_load<2 >(sh, 0, i, j0, f4, tg); __syncthreads();
    col_acc <2 >(sh, kw, b_levels[1], base, f4, acc); __syncthreads();
    col_load<4 >(sh, 1, i, j0, f4, tg); __syncthreads();
    col_acc <4 >(sh, kw, b_levels[2], base, f4, acc); __syncthreads();
    col_load<8 >(sh, 2, i, j0, f4, tg); __syncthreads();
    col_acc <8 >(sh, kw, b_levels[3], base, f4, acc); __syncthreads();
    col_load<16>(sh, 3, i, j0, f4, tg); __syncthreads();
    col_acc <16>(sh, kw, b_levels[4], base, f4, acc); __syncthreads();
    col_load<32>(sh, 4, i, j0, f4, tg); __syncthreads();
    col_acc <32>(sh, kw, b_levels[5], base, f4, acc);

#pragma unroll
    for (int q = 0; q < 8; q++) {
        uint4 u;
        u.x = f2tf32(acc[q].x); u.y = f2tf32(acc[q].y);
        u.z = f2tf32(acc[q].z); u.w = f2tf32(acc[q].w);
        *reinterpret_cast<uint4*>(&Gs[(base + q) * 132 + 4 * f4]) = u;
    }
    __syncthreads();

    int w    = t >> 5;
    int lane = t & 31;
    int mt   = w & 3;
    int nh   = w >> 2;
    int g    = lane >> 2;
    int tig  = lane & 3;

    float d[8][4];
#pragma unroll
    for (int nt = 0; nt < 8; nt++)
#pragma unroll
        for (int e = 0; e < 4; e++) d[nt][e] = 0.0f;

#pragma unroll 4
    for (int kk = 0; kk < 16; kk++) {
        int arow = (mt * 16 + g) * 132 + kk * 8 + tig;
        unsigned a0 = Gs[arow];
        unsigned a1 = Gs[arow + 8 * 132];
        unsigned a2 = Gs[arow + 4];
        unsigned a3 = Gs[arow + 8 * 132 + 4];
        int brow = (kk * 4 + tig) * 132 + nh * 64 + g;
#pragma unroll
        for (int nt = 0; nt < 8; nt++) {
            uint2 b = W1p[brow + nt * 8];
            mma_tf32(d[nt], a0, a1, a2, a3, b.x, b.y);
        }
    }

    __half2* Hs2 = (__half2*)smem_raw;
    int m0 = mt * 16 + g;
#pragma unroll
    for (int nt = 0; nt < 8; nt++) {
        int n0 = nh * 64 + nt * 8 + 2 * tig;
        float bb0 = b1s[n0], bb1 = b1s[n0 + 1];
        Hs2[m0 * 68 + (n0 >> 1)]       = __floats2half2_rn(d[nt][0] + bb0,
                                                           d[nt][1] + bb1);
        Hs2[(m0 + 8) * 68 + (n0 >> 1)] = __floats2half2_rn(d[nt][2] + bb0,
                                                           d[nt][3] + bb1);
    }
    __syncthreads();

    const uint4* Hs4 = (const uint4*)smem_raw;
#pragma unroll
    for (int it = 0; it < 4; it++) {
        int task = it * 256 + t;
        int p  = task >> 4;
        int q4 = task & 15;
        g_Hh[((size_t)(i * R + j0 + p)) * 16 + q4] = Hs4[p * 17 + q4];
    }
}

// ---------------------------------------------------------------------------
// Points: bilerp gather of fp16 H + relu + W2 + b2.
// CHANGED: launch_bounds(256,4) to force 4 CTAs/SM; W2 genuinely smem-resident.
// ---------------------------------------------------------------------------
__device__ __forceinline__ void acc_corner(uint4 c, float wgt, float* v)
{
    __half2 h0 = *reinterpret_cast<const __half2*>(&c.x);
    __half2 h1 = *reinterpret_cast<const __half2*>(&c.y);
    __half2 h2 = *reinterpret_cast<const __half2*>(&c.z);
    __half2 h3 = *reinterpret_cast<const __half2*>(&c.w);
    float2 f0 = __half22float2(h0);
    float2 f1 = __half22float2(h1);
    float2 f2 = __half22float2(h2);
    float2 f3 = __half22float2(h3);
    v[0] += wgt * f0.x; v[1] += wgt * f0.y;
    v[2] += wgt * f1.x; v[3] += wgt * f1.y;
    v[4] += wgt * f2.x; v[5] += wgt * f2.y;
    v[6] += wgt * f3.x; v[7] += wgt * f3.y;
}

__global__ void __launch_bounds__(256, 4) k_pts(const float* __restrict__ pt,
                                                const float4* __restrict__ W2v,
                                                const float* __restrict__ b2,
                                                float4* __restrict__ out4)
{
    __shared__ float4 w2s[128];
    int t = threadIdx.x, lane = t & 31, w = t >> 5;
    int lh = lane >> 4;
    int lf = lane & 15;

    if (t < 128) w2s[t] = W2v[t];
    __syncthreads();

    float b20 = b2[0], b21 = b2[1], b22 = b2[2], b23 = b2[3];

    int p0 = blockIdx.x * 128 + w * 16 + lh;
#pragma unroll 2
    for (int it = 0; it < 8; it++) {
        int p = p0 + it * 2;
        float px = pt[2 * p];
        float py = pt[2 * p + 1];
        float ax = (px + 1.0f) / 2.0f * 255.0f;
        float ay = (py + 1.0f) / 2.0f * 255.0f;
        int ix = (int)ax; if (ix > 255) ix = 255;
        int iy = (int)ay; if (iy > 255) iy = 255;
        float fx = ax - (float)ix;
        float fy = ay - (float)iy;
        int ix1 = (ix + 1 > 255) ? 255 : ix + 1;
        int iy1 = (iy + 1 > 255) ? 255 : iy + 1;
        float w00 = (1.0f - fx) * (1.0f - fy);
        float w01 = (1.0f - fx) * fy;
        float w10 = fx * (1.0f - fy);
        float w11 = fx * fy;

        uint4 c00 = g_Hh[((size_t)(ix  * R + iy )) * 16 + lf];
        uint4 c01 = g_Hh[((size_t)(ix  * R + iy1)) * 16 + lf];
        uint4 c10 = g_Hh[((size_t)(ix1 * R + iy )) * 16 + lf];
        uint4 c11 = g_Hh[((size_t)(ix1 * R + iy1)) * 16 + lf];

        float v[8];
#pragma unroll
        for (int k = 0; k < 8; k++) v[k] = 0.0f;
        acc_corner(c00, w00, v);
        acc_corner(c01, w01, v);
        acc_corner(c10, w10, v);
        acc_corner(c11, w11, v);

        float4 o = make_float4(0.f, 0.f, 0.f, 0.f);
#pragma unroll
        for (int j = 0; j < 8; j++) {
            float h = fmaxf(v[j], 0.0f);
            float4 w2r = w2s[lf * 8 + j];
            o.x += h * w2r.x; o.y += h * w2r.y;
            o.z += h * w2r.z; o.w += h * w2r.w;
        }

#pragma unroll
        for (int off = 8; off; off >>= 1) {
            o.x += __shfl_xor_sync(0xffffffffu, o.x, off);
            o.y += __shfl_xor_sync(0xffffffffu, o.y, off);
            o.z += __shfl_xor_sync(0xffffffffu, o.z, off);
            o.w += __shfl_xor_sync(0xffffffffu, o.w, off);
        }
        if (lf == 0)
            out4[p] = make_float4(o.x + b20, o.y + b21, o.z + b22, o.w + b23);
    }
}

// ---------------------------------------------------------------------------
static void fill_kw(KW& kw)
{
    for (int l = 1; l <= 5; l++) {
        int s = 1 << l;
        int off = s - 2;
        double stdv = s * 0.5;
        double tmp[32];
        double sum = 0.0;
        for (int n = 0; n < s; n++) {
            double x = ((double)n - (s - 1) * 0.5) / stdv;
            tmp[n] = exp(-0.5 * x * x);
            sum += tmp[n];
        }
        for (int n = 0; n < s; n++) kw.w[off + n] = (float)(tmp[n] / sum);
    }
}

extern "C" void kernel_launch(void* const* d_in, const int* in_sizes, int n_in,
                              void* d_out, int out_size) {
    const float*  pt       = (const float*)d_in[0];
    const float4* base4    = (const float4*)d_in[1];
    const float*  b_levels = (const float*)d_in[2];
    const float*  W1       = (const float*)d_in[3];
    const float*  b1       = (const float*)d_in[4];
    const float*  W2       = (const float*)d_in[5];
    const float*  b2       = (const float*)d_in[6];
    float* out             = (float*)d_out;

    KW kw;
    fill_kw(kw);

    cudaFuncSetAttribute(k_colsH, cudaFuncAttributeMaxDynamicSharedMemorySize,
                         SMEM_CH);

    dim3 bg(256, 4);
    k_rows<<<bg, 512>>>(base4, kw);
    k_colsH<<<bg, 256, SMEM_CH>>>(base4, b_levels, W1, b1, kw);
    k_pts<<<2048, 256>>>(pt, (const float4*)W2, b2, (float4*)out);
}

// round 8
// speedup vs baseline: 1.2372x; 1.0507x over previous
#include <cuda_runtime.h>
#include <cuda_fp16.h>
#include <math.h>

#define R 256
#define F4 32           // 128 features = 32 float4
#define NPIX (R * R)

// Static device scratch
__device__ uint2 g_tmph[5 * (size_t)NPIX * F4];  // row-blurred levels, fp16x4 (84 MB)
__device__ uint4 g_Hh[(size_t)NPIX * 16];        // H = G@W1+b1, fp16 (16.8 MB)

// ---------------------------------------------------------------------------
// Compile-time gaussian weights -> FFMA-immediate taps (rt_SMSP=1 vs 2)
// ---------------------------------------------------------------------------
constexpr double cexp_d(double x) {   // x <= 0
    double r = x; int k = 0;
    while (r < -0.34657359027997264) { r += 0.69314718055994530942; k++; }
    double term = 1.0, sum = 1.0;
    for (int i = 1; i < 22; i++) { term *= r / (double)i; sum += term; }
    for (int i = 0; i < k; i++) sum *= 0.5;
    return sum;
}

template <int S> struct GWt {
    float w[S];
    constexpr GWt() : w{} {
        double t[S] = {};
        double sum = 0.0;
        for (int n = 0; n < S; n++) {
            double xx = ((double)n - (double)(S - 1) * 0.5) / ((double)S * 0.5);
            t[n] = cexp_d(-0.5 * xx * xx);
            sum += t[n];
        }
        for (int n = 0; n < S; n++) w[n] = (float)(t[n] / sum);
    }
};

__device__ __forceinline__ int reflect_i(int c) {
    c = (c < 0) ? -c : c;
    return (c > R - 1) ? (2 * (R - 1) - c) : c;
}

__device__ __forceinline__ uint2 pack4(float4 v) {
    __half2 a = __floats2half2_rn(v.x, v.y);
    __half2 b = __floats2half2_rn(v.z, v.w);
    uint2 r;
    r.x = *reinterpret_cast<unsigned*>(&a);
    r.y = *reinterpret_cast<unsigned*>(&b);
    return r;
}

__device__ __forceinline__ float4 unpack4(uint2 u) {
    __half2 a = *reinterpret_cast<__half2*>(&u.x);
    __half2 b = *reinterpret_cast<__half2*>(&u.y);
    float2 fa = __half22float2(a);
    float2 fb = __half22float2(b);
    return make_float4(fa.x, fa.y, fb.x, fb.y);
}

__device__ __forceinline__ unsigned f2tf32(float f) {
    unsigned u;
    asm("cvt.rna.tf32.f32 %0, %1;" : "=r"(u) : "f"(f));
    return u;
}

__device__ __forceinline__ void mma_tf32(float* d, unsigned a0, unsigned a1,
                                         unsigned a2, unsigned a3,
                                         unsigned b0, unsigned b1) {
    asm("mma.sync.aligned.m16n8k8.row.col.f32.tf32.tf32.f32 "
        "{%0,%1,%2,%3},{%4,%5,%6,%7},{%8,%9},{%0,%1,%2,%3};"
        : "+f"(d[0]), "+f"(d[1]), "+f"(d[2]), "+f"(d[3])
        : "r"(a0), "r"(a1), "r"(a2), "r"(a3), "r"(b0), "r"(b1));
}

// ---------------------------------------------------------------------------
// Row pass, all 5 levels fused. 512 threads, 4 rows per thread.
// (R4 structure; ONLY change: immediate weights)
// ---------------------------------------------------------------------------
template <int S>
__device__ __forceinline__ void row_level(const float4 (*sh)[F4],
                                          int base, int f4, int lvl, int i0, int j)
{
    constexpr GWt<S> gw{};
    float4 acc[4];
#pragma unroll
    for (int q = 0; q < 4; q++) acc[q] = make_float4(0.f, 0.f, 0.f, 0.f);
#pragma unroll
    for (int r = 0; r < 4 + S - 1; r++) {
        float4 v = sh[base + 16 - S / 2 + r][f4];
#pragma unroll
        for (int q = 0; q < 4; q++) {
            int jj = r - q;
            if (jj >= 0 && jj < S) {
                float k = gw.w[jj];              // immediate operand
                acc[q].x += k * v.x; acc[q].y += k * v.y;
                acc[q].z += k * v.z; acc[q].w += k * v.w;
            }
        }
    }
    size_t lb = (size_t)lvl * NPIX * F4;
#pragma unroll
    for (int q = 0; q < 4; q++)
        g_tmph[lb + ((size_t)(i0 + base + q) * R + j) * F4 + f4] = pack4(acc[q]);
}

__global__ void __launch_bounds__(512, 2) k_rows(const float4* __restrict__ in)
{
    __shared__ float4 sh[96][F4];
    int j  = blockIdx.x;
    int i0 = blockIdx.y * 64;
    int t  = threadIdx.x;
    int f4 = t & 31, tg = t >> 5;           // tg 0..15

    for (int rr = tg; rr < 96; rr += 16) {
        int c = reflect_i(i0 - 16 + rr);
        sh[rr][f4] = in[((size_t)c * R + j) * F4 + f4];
    }
    __syncthreads();

    int base = tg * 4;
    row_level<2 >(sh, base, f4, 0, i0, j);
    row_level<4 >(sh, base, f4, 1, i0, j);
    row_level<8 >(sh, base, f4, 2, i0, j);
    row_level<16>(sh, base, f4, 3, i0, j);
    row_level<32>(sh, base, f4, 4, i0, j);
}

// ---------------------------------------------------------------------------
// Col pass + H GEMM fused (R4 structure; ONLY change: immediate weights with
// per-level temp accumulator, post-scaled by b_l).
// ---------------------------------------------------------------------------
#define SMEM_CH 151040

template <int S>
__device__ __forceinline__ void col_load(float4 (*sh)[F4], int lvl, int i, int j0,
                                         int f4, int tg)
{
    size_t lb = (size_t)lvl * NPIX * F4;
#pragma unroll
    for (int rr = tg; rr < 96; rr += 8) {
        int c = reflect_i(j0 - 16 + rr);
        sh[rr][f4] = unpack4(g_tmph[lb + ((size_t)i * R + c) * F4 + f4]);
    }
}

template <int S>
__device__ __forceinline__ void col_acc(const float4 (*sh)[F4],
                                        float bl, int base, int f4, float4* acc)
{
    constexpr GWt<S> gw{};
    float4 tmp[8];
#pragma unroll
    for (int q = 0; q < 8; q++) tmp[q] = make_float4(0.f, 0.f, 0.f, 0.f);
#pragma unroll
    for (int r = 0; r < 8 + S - 1; r++) {
        float4 v = sh[base + 16 - S / 2 + r][f4];
#pragma unroll
        for (int q = 0; q < 8; q++) {
            int jj = r - q;
            if (jj >= 0 && jj < S) {
                float k = gw.w[jj];              // immediate operand
                tmp[q].x += k * v.x; tmp[q].y += k * v.y;
                tmp[q].z += k * v.z; tmp[q].w += k * v.w;
            }
        }
    }
#pragma unroll
    for (int q = 0; q < 8; q++) {
        acc[q].x += bl * tmp[q].x; acc[q].y += bl * tmp[q].y;
        acc[q].z += bl * tmp[q].z; acc[q].w += bl * tmp[q].w;
    }
}

__global__ void __launch_bounds__(256, 1) k_colsH(const float4* __restrict__ base4,
                                                  const float* __restrict__ b_levels,
                                                  const float* __restrict__ W1,
                                                  const float* __restrict__ b1)
{
    extern __shared__ unsigned char smem_raw[];
    float4 (*sh)[F4]   = (float4 (*)[F4])smem_raw;
    uint2*    W1p      = (uint2*)(smem_raw + 49152);
    unsigned* Gs       = (unsigned*)(smem_raw + 116736);
    float*    b1s      = (float*)(smem_raw + 150528);

    int i  = blockIdx.x;
    int j0 = blockIdx.y * 64;
    int t  = threadIdx.x;
    int f4 = t & 31, tg = t >> 5;
    int base = tg * 8;

#pragma unroll
    for (int it = 0; it < 32; it++) {
        int task = it * 256 + t;
        int r = task >> 7;
        int n = task & 127;
        int klo = 8 * (r >> 2) + (r & 3);
        uint2 v;
        v.x = f2tf32(W1[klo * 128 + n]);
        v.y = f2tf32(W1[(klo + 4) * 128 + n]);
        W1p[r * 132 + n] = v;
    }
    if (t < 128) b1s[t] = b1[t];

    float b0 = b_levels[0];
    float4 acc[8];
#pragma unroll
    for (int q = 0; q < 8; q++) {
        float4 v = base4[((size_t)i * R + (j0 + base + q)) * F4 + f4];
        acc[q] = make_float4(b0 * v.x, b0 * v.y, b0 * v.z, b0 * v.w);
    }

    col_load<2 >(sh, 0, i, j0, f4, tg); __syncthreads();
    col_acc <2 >(sh, b_levels[1], base, f4, acc); __syncthreads();
    col_load<4 >(sh, 1, i, j0, f4, tg); __syncthreads();
    col_acc <4 >(sh, b_levels[2], base, f4, acc); __syncthreads();
    col_load<8 >(sh, 2, i, j0, f4, tg); __syncthreads();
    col_acc <8 >(sh, b_levels[3], base, f4, acc); __syncthreads();
    col_load<16>(sh, 3, i, j0, f4, tg); __syncthreads();
    col_acc <16>(sh, b_levels[4], base, f4, acc); __syncthreads();
    col_load<32>(sh, 4, i, j0, f4, tg); __syncthreads();
    col_acc <32>(sh, b_levels[5], base, f4, acc);

#pragma unroll
    for (int q = 0; q < 8; q++) {
        uint4 u;
        u.x = f2tf32(acc[q].x); u.y = f2tf32(acc[q].y);
        u.z = f2tf32(acc[q].z); u.w = f2tf32(acc[q].w);
        *reinterpret_cast<uint4*>(&Gs[(base + q) * 132 + 4 * f4]) = u;
    }
    __syncthreads();

    int w    = t >> 5;
    int lane = t & 31;
    int mt   = w & 3;
    int nh   = w >> 2;
    int g    = lane >> 2;
    int tig  = lane & 3;

    float d[8][4];
#pragma unroll
    for (int nt = 0; nt < 8; nt++)
#pragma unroll
        for (int e = 0; e < 4; e++) d[nt][e] = 0.0f;

#pragma unroll 4
    for (int kk = 0; kk < 16; kk++) {
        int arow = (mt * 16 + g) * 132 + kk * 8 + tig;
        unsigned a0 = Gs[arow];
        unsigned a1 = Gs[arow + 8 * 132];
        unsigned a2 = Gs[arow + 4];
        unsigned a3 = Gs[arow + 8 * 132 + 4];
        int brow = (kk * 4 + tig) * 132 + nh * 64 + g;
#pragma unroll
        for (int nt = 0; nt < 8; nt++) {
            uint2 b = W1p[brow + nt * 8];
            mma_tf32(d[nt], a0, a1, a2, a3, b.x, b.y);
        }
    }

    __half2* Hs2 = (__half2*)smem_raw;
    int m0 = mt * 16 + g;
#pragma unroll
    for (int nt = 0; nt < 8; nt++) {
        int n0 = nh * 64 + nt * 8 + 2 * tig;
        float bb0 = b1s[n0], bb1 = b1s[n0 + 1];
        Hs2[m0 * 68 + (n0 >> 1)]       = __floats2half2_rn(d[nt][0] + bb0,
                                                           d[nt][1] + bb1);
        Hs2[(m0 + 8) * 68 + (n0 >> 1)] = __floats2half2_rn(d[nt][2] + bb0,
                                                           d[nt][3] + bb1);
    }
    __syncthreads();

    const uint4* Hs4 = (const uint4*)smem_raw;
#pragma unroll
    for (int it = 0; it < 4; it++) {
        int task = it * 256 + t;
        int p  = task >> 4;
        int q4 = task & 15;
        g_Hh[((size_t)(i * R + j0 + p)) * 16 + q4] = Hs4[p * 17 + q4];
    }
}

// ---------------------------------------------------------------------------
// Points: bilerp gather of fp16 H + relu + W2 + b2.  (R4 exact)
// ---------------------------------------------------------------------------
__global__ void __launch_bounds__(256) k_pts(const float* __restrict__ pt,
                                             const float4* __restrict__ W2v,
                                             const float* __restrict__ b2,
                                             float4* __restrict__ out4)
{
    int t = threadIdx.x, lane = t & 31, w = t >> 5;
    int lh = lane >> 4;
    int lf = lane & 15;

    float4 w2r[8];
#pragma unroll
    for (int j = 0; j < 8; j++) w2r[j] = W2v[lf * 8 + j];
    float b20 = b2[0], b21 = b2[1], b22 = b2[2], b23 = b2[3];

    int p0 = blockIdx.x * 128 + w * 16 + lh;
#pragma unroll 2
    for (int it = 0; it < 8; it++) {
        int p = p0 + it * 2;
        float px = pt[2 * p];
        float py = pt[2 * p + 1];
        float ax = (px + 1.0f) / 2.0f * 255.0f;
        float ay = (py + 1.0f) / 2.0f * 255.0f;
        int ix = (int)ax; if (ix > 255) ix = 255;
        int iy = (int)ay; if (iy > 255) iy = 255;
        float fx = ax - (float)ix;
        float fy = ay - (float)iy;
        int ix1 = (ix + 1 > 255) ? 255 : ix + 1;
        int iy1 = (iy + 1 > 255) ? 255 : iy + 1;
        float w00 = (1.0f - fx) * (1.0f - fy);
        float w01 = (1.0f - fx) * fy;
        float w10 = fx * (1.0f - fy);
        float w11 = fx * fy;

        uint4 c00 = g_Hh[((size_t)(ix  * R + iy )) * 16 + lf];
        uint4 c01 = g_Hh[((size_t)(ix  * R + iy1)) * 16 + lf];
        uint4 c10 = g_Hh[((size_t)(ix1 * R + iy )) * 16 + lf];
        uint4 c11 = g_Hh[((size_t)(ix1 * R + iy1)) * 16 + lf];

        float v[8];
#pragma unroll
        for (int k = 0; k < 8; k++) v[k] = 0.0f;
        {
            const unsigned* cs[4] = {&c00.x, &c01.x, &c10.x, &c11.x};
            float ws[4] = {w00, w01, w10, w11};
#pragma unroll
            for (int cc = 0; cc < 4; cc++) {
                float wgt = ws[cc];
#pragma unroll
                for (int k = 0; k < 4; k++) {
                    __half2 h = *reinterpret_cast<const __half2*>(&cs[cc][k]);
                    float2 f = __half22float2(h);
                    v[2 * k]     += wgt * f.x;
                    v[2 * k + 1] += wgt * f.y;
                }
            }
        }

        float4 o = make_float4(0.f, 0.f, 0.f, 0.f);
#pragma unroll
        for (int j = 0; j < 8; j++) {
            float h = fmaxf(v[j], 0.0f);
            o.x += h * w2r[j].x; o.y += h * w2r[j].y;
            o.z += h * w2r[j].z; o.w += h * w2r[j].w;
        }

#pragma unroll
        for (int off = 8; off; off >>= 1) {
            o.x += __shfl_xor_sync(0xffffffffu, o.x, off);
            o.y += __shfl_xor_sync(0xffffffffu, o.y, off);
            o.z += __shfl_xor_sync(0xffffffffu, o.z, off);
            o.w += __shfl_xor_sync(0xffffffffu, o.w, off);
        }
        if (lf == 0)
            out4[p] = make_float4(o.x + b20, o.y + b21, o.z + b22, o.w + b23);
    }
}

// ---------------------------------------------------------------------------
extern "C" void kernel_launch(void* const* d_in, const int* in_sizes, int n_in,
                              void* d_out, int out_size) {
    const float*  pt       = (const float*)d_in[0];
    const float4* base4    = (const float4*)d_in[1];
    const float*  b_levels = (const float*)d_in[2];
    const float*  W1       = (const float*)d_in[3];
    const float*  b1       = (const float*)d_in[4];
    const float*  W2       = (const float*)d_in[5];
    const float*  b2       = (const float*)d_in[6];
    float* out             = (float*)d_out;

    cudaFuncSetAttribute(k_colsH, cudaFuncAttributeMaxDynamicSharedMemorySize,
                         SMEM_CH);

    dim3 bg(256, 4);
    k_rows<<<bg, 512>>>(base4);
    k_colsH<<<bg, 256, SMEM_CH>>>(base4, b_levels, W1, b1);
    k_pts<<<2048, 256>>>(pt, (const float4*)W2, b2, (float4*)out);
}